// round 15
// baseline (speedup 1.0000x reference)
#include <cuda_runtime.h>
#include <cstdint>
#include <cstddef>

// CRF forward log-partition. B=512, T=1024, L=64.
// Fwd/bwd split (halves the serial chain) + ROW-SPLIT (2 warps per chain
// direction; lane owns ONE output row) + length-aware placement.
//   Z = e63^T M_{len-1}..M_0 delta,  M_t = diag(el_t) E.
//   fwd chain: p = M_{m-1}..M_0 delta_start      (m = len/2 steps)
//   bwd chain: v = M_m^T..M_{len-1}^T e63        (len-m steps, E^T rows)
//   logZ = (ktF+ktB)*ln2 + log( sum_j p[j] * v[j] )
// CTA = 256 threads = 8 warps = 4 chains (2 batches x fwd/bwd); warp w
// handles rows (w&1)*32..+31 of chain w>>1. Each chain syncs its two warps
// with a named barrier each step (bar.sync id,64). Per-warp step work is
// HALVED vs R14: 16x ld.shared.v2.b64 (broadcast) + 32 FMA2 + 1 ex2 + STS.32.
// Rescale every 4 steps, deferred; cross-warp max via two smem slots
// (REC writes pre-bar, FOLD reads post-bar next group).
// Placement: pair rank == blockIdx (longest pairs = wave 1, one CTA/SM);
// wave-2 short CTAs are work-stolen onto SMs that finish early.

#define CRF_B 512
#define CRF_T 1024
#define CRF_L 64
#define C_LOG2E 1.4426950408889634f
#define C_LN2   0.6931471805599453f
#define FULLM  0xffffffffu

using u64 = unsigned long long;

__device__ int d_perm[CRF_B];            // rank -> batch index

__device__ __forceinline__ float ex2f(float x) {
    float r; asm("ex2.approx.f32 %0, %1;" : "=f"(r) : "f"(x)); return r;
}
__device__ __forceinline__ u64 packf2(float lo, float hi) {
    u64 r; asm("mov.b64 %0, {%1, %2};" : "=l"(r) : "f"(lo), "f"(hi)); return r;
}
__device__ __forceinline__ void unpackf2(u64 v, float& lo, float& hi) {
    asm("mov.b64 {%0, %1}, %2;" : "=f"(lo), "=f"(hi) : "l"(v));
}
__device__ __forceinline__ uint32_t smem_u32(const void* p) {
    uint32_t a;
    asm("{ .reg .u64 t; cvta.to.shared.u64 t, %1; cvt.u32.u64 %0, t; }"
        : "=r"(a) : "l"(p));
    return a;
}
#define FMA2(acc, a, b) \
    asm("fma.rn.f32x2 %0, %1, %2, %0;" : "+l"(acc) : "l"(a), "l"(b))
#define ADD2(acc, a) \
    asm("add.rn.f32x2 %0, %0, %1;" : "+l"(acc) : "l"(a))
#define LDSV2(lo, hi, addr) \
    asm volatile("ld.shared.v2.b64 {%0, %1}, [%2];" \
                 : "=l"(lo), "=l"(hi) : "r"(addr))
#define BAR64(id) \
    asm volatile("bar.sync %0, 64;" :: "r"(id) : "memory")

// ---- pre-kernel: exact descending-length ranking (O(n^2) count) ----
__global__ void __launch_bounds__(CRF_B)
rank_kernel(const int* __restrict__ lens)
{
    __shared__ int sl[CRF_B];
    const int i = threadIdx.x;
    sl[i] = lens[i];
    __syncthreads();
    const int li = sl[i];
    int cnt = 0;
#pragma unroll 8
    for (int j = 0; j < CRF_B; j++) {
        int lj = sl[j];
        cnt += (lj > li) || (lj == li && j < i);
    }
    d_perm[cnt] = i;                      // bijection: rank -> batch
}

// One row-split CRF step: this warp computes rows half*32..+31 of the chain.
// lg = this lane's logit (prefetched). FOLD: combine the two halves' recorded
// maxima (bar-separated -> visible), fold exact 2^-k into el. REC: per-warp
// REDUX of new p into smaxC[half] (pre-bar; consumed next group).
template <bool FOLD, bool REC>
__device__ __forceinline__ void crf_step(
    float lg, const u64 (&E)[32],
    uint32_t rda, uint32_t wra,
    unsigned* __restrict__ smaxC,
    int row, int half, int barid, int& ktot)
{
    float el = ex2f(lg * C_LOG2E);
    if (FOLD) {
        unsigned mu = max(smaxC[0], smaxC[1]);   // positive floats: uint cmp ok
        int k = (int)(mu >> 23) - 127;
        ktot += k;
        el *= __int_as_float((127 - k) << 23);   // exact 2^-k
    }

    // ---- 16 back-to-back LDS.128 broadcasts (all 64 p values) ----
    u64 p[32];
#pragma unroll
    for (int i = 0; i < 16; i++)
        LDSV2(p[2 * i], p[2 * i + 1], rda + 16u * i);

    u64 c0 = 0ull, c1 = 0ull, c2 = 0ull, c3 = 0ull;
#pragma unroll
    for (int j = 0; j < 32; j += 4) {
        FMA2(c0, E[j],     p[j]);
        FMA2(c1, E[j + 1], p[j + 1]);
        FMA2(c2, E[j + 2], p[j + 2]);
        FMA2(c3, E[j + 3], p[j + 3]);
    }
    ADD2(c0, c1); ADD2(c2, c3); ADD2(c0, c2);
    float ev, od;
    unpackf2(c0, ev, od);
    float pn = (ev + od) * el;                   // new p[row]

    asm volatile("st.shared.f32 [%0], %1;"
                 :: "r"(wra + 4u * (uint32_t)row), "f"(pn));

    if (REC) {
        unsigned mu = __reduce_max_sync(FULLM, __float_as_uint(pn));
        if ((threadIdx.x & 31) == 0) smaxC[half] = mu;
    }
    BAR64(barid);
}

// Runs nlog logit steps (this lane's scalar logit, stride SGN*64 floats),
// then optional bare step (lg = 0 -> el = 1). Groups of 4: FOLD,-,-,REC.
template <int SGN>
__device__ __forceinline__ int run_chain(
    const float* __restrict__ lgp, int nlog, bool bare,
    const u64 (&E)[32],
    uint32_t a0, uint32_t a1,
    unsigned* __restrict__ smaxC, int row, int half, int barid)
{
    int ktot = 0;

    float q0, q1, q2, q3;
    if (nlog > 0) q0 = __ldg(lgp);
    if (nlog > 1) q1 = __ldg(lgp + SGN * 64);
    if (nlog > 2) q2 = __ldg(lgp + SGN * 128);
    if (nlog > 3) q3 = __ldg(lgp + SGN * 192);

    int t = 0;
    for (; t + 4 <= nlog; t += 4) {
        float g;
        g = q0; if (t + 4 < nlog) q0 = __ldg(lgp + (ptrdiff_t)SGN * (t + 4) * 64);
        crf_step<true,  false>(g, E, a0, a1, smaxC, row, half, barid, ktot);
        g = q1; if (t + 5 < nlog) q1 = __ldg(lgp + (ptrdiff_t)SGN * (t + 5) * 64);
        crf_step<false, false>(g, E, a1, a0, smaxC, row, half, barid, ktot);
        g = q2; if (t + 6 < nlog) q2 = __ldg(lgp + (ptrdiff_t)SGN * (t + 6) * 64);
        crf_step<false, false>(g, E, a0, a1, smaxC, row, half, barid, ktot);
        g = q3; if (t + 7 < nlog) q3 = __ldg(lgp + (ptrdiff_t)SGN * (t + 7) * 64);
        crf_step<false, true >(g, E, a1, a0, smaxC, row, half, barid, ktot);
    }

    bool pend = (t > 0);
    if (t < nlog) {
        if (pend) crf_step<true,  false>(q0, E, a0, a1, smaxC, row, half, barid, ktot);
        else      crf_step<false, false>(q0, E, a0, a1, smaxC, row, half, barid, ktot);
        pend = false; t++;
    }
    if (t < nlog) { crf_step<false, false>(q1, E, a1, a0, smaxC, row, half, barid, ktot); t++; }
    if (t < nlog) { crf_step<false, false>(q2, E, a0, a1, smaxC, row, half, barid, ktot); t++; }

    if (bare) {
        bool odd = (t & 1);
        if (pend) {
            if (odd) crf_step<true, false>(0.0f, E, a1, a0, smaxC, row, half, barid, ktot);
            else     crf_step<true, false>(0.0f, E, a0, a1, smaxC, row, half, barid, ktot);
        } else {
            if (odd) crf_step<false, false>(0.0f, E, a1, a0, smaxC, row, half, barid, ktot);
            else     crf_step<false, false>(0.0f, E, a0, a1, smaxC, row, half, barid, ktot);
        }
    }
    return ktot;
}

__global__ void __launch_bounds__(256)
crf_fwd_kernel(const float* __restrict__ logits,
               const int*   __restrict__ lens,
               const float* __restrict__ trans,
               float*       __restrict__ out)
{
    __shared__ __align__(16) float sp[4][2][CRF_L];  // [chain][buffer][row]
    __shared__ unsigned smaxU[4][2];                 // [chain][half]
    __shared__ int      ktW[4];                      // [chain]
    __shared__ int      bufW[4];                     // [chain] final buffer

    const int w     = threadIdx.x >> 5;              // 0..7
    const int lane  = threadIdx.x & 31;
    const int chain = w >> 1;                        // 0..3
    const int dir   = chain & 1;                     // 0 = fwd, 1 = bwd
    const int bi    = chain >> 1;                    // batch within CTA
    const int half  = w & 1;
    const int row   = half * 32 + lane;              // owned output row
    const int barid = chain + 1;                     // named barrier per chain

    // ---- placement: pair rank == blockIdx (longest pairs in wave 1) ----
    const int pair = blockIdx.x;                     // grid = 256
    const int b    = d_perm[2 * pair + bi];

    const uint32_t a0 = smem_u32(sp[chain][0]);
    const uint32_t a1 = smem_u32(sp[chain][1]);
    unsigned* smaxC = smaxU[chain];

    const int len = lens[b];
    const int m   = len >> 1;                        // fwd steps; bwd = len-m

    // ---- E row in registers: fwd = exp(trans[row,:]); bwd = exp(trans[:,row])
    u64 E[32];
    if (dir == 0) {
        const float* r0 = trans + row * CRF_L;
#pragma unroll
        for (int j = 0; j < 32; j++)
            E[j] = packf2(expf(r0[2 * j]), expf(r0[2 * j + 1]));
    } else {
        const float* c0p = trans + row;              // column 'row'
#pragma unroll
        for (int j = 0; j < 32; j++)
            E[j] = packf2(expf(c0p[(2 * j) * CRF_L]), expf(c0p[(2 * j + 1) * CRF_L]));
    }

    const float* base = logits + (size_t)b * CRF_T * CRF_L + row;

    // ---- init chain state + smax, then barrier ----
    if (dir == 0) {
        sp[chain][0][row] = (row == 62) ? 1.0f : 0.0f;
    } else {
        float e63 = expf(trans[63 * CRF_L + row]);
        if (len >= 1) e63 *= expf(__ldg(base + (ptrdiff_t)(len - 1) * CRF_L));
        sp[chain][0][row] = e63;
    }
    if (lane == 0) smaxC[half] = 0x3f800000u;        // 1.0f -> first fold k=0
    BAR64(barid);

    int kt;
    int nsteps;

    if (dir == 0) {
        kt = run_chain<+1>(base, m, false, E, a0, a1, smaxC, row, half, barid);
        nsteps = m;
    } else {
        const int nlog = (len >= 1) ? (len - m - 1) : 0;
        const float* lgb = base + (ptrdiff_t)(len - 2) * CRF_L;
        kt = run_chain<-1>(lgb, nlog, len >= 1, E, a0, a1, smaxC, row, half, barid);
        nsteps = (len >= 1) ? (nlog + 1) : 0;
    }

    if (lane == 0 && half == 0) {
        ktW[chain]  = kt;
        bufW[chain] = nsteps & 1;
    }
    __syncthreads();

    // ---- combine per batch: logZ = (ktF+ktB)*ln2 + log(sum pF[j]*pB[j]) ----
    if (w == 4 * bi && chain == 2 * bi) {            // warp 0 of each batch
        const float* pf = sp[2 * bi][bufW[2 * bi]];
        const float* pb = sp[2 * bi + 1][bufW[2 * bi + 1]];
        float2 f = reinterpret_cast<const float2*>(pf)[lane];
        float2 g = reinterpret_cast<const float2*>(pb)[lane];
        float dot = f.x * g.x + f.y * g.y;
#pragma unroll
        for (int o = 16; o > 0; o >>= 1)
            dot += __shfl_xor_sync(FULLM, dot, o);
        if (lane == 0)
            out[b] = (float)(ktW[2 * bi] + ktW[2 * bi + 1]) * C_LN2 + __logf(dot);
    }
}

extern "C" void kernel_launch(void* const* d_in, const int* in_sizes, int n_in,
                              void* d_out, int out_size)
{
    const float* logits = (const float*)d_in[0];   // [512,1024,64] f32
    const int*   lens   = (const int*)  d_in[1];   // [512] i32
    const float* trans  = (const float*)d_in[2];   // [64,64] f32
    float* out = (float*)d_out;                    // [512] f32

    rank_kernel<<<1, CRF_B>>>(lens);
    crf_fwd_kernel<<<CRF_B / 2, 256>>>(logits, lens, trans, out);
}

// round 16
// speedup vs baseline: 1.1229x; 1.1229x over previous
#include <cuda_runtime.h>
#include <cstdint>
#include <cstddef>

// CRF forward log-partition. B=512, T=1024, L=64.
// Round-14 structure (best: 105us) with the per-step __syncwarp REMOVED:
// each chain lives in ONE converged warp; STS and the next step's LDS are
// both volatile asm (compiler-ordered) and the SM LSU is in-order per warp,
// so the cross-lane hand-off is already correct without WARPSYNC (~23cyc
// saved on every serial step).
//
// Fwd/bwd split (halves the serial chain) + length-aware placement +
// full-SMSP spread:
//  - pre-kernel ranks batches by len desc (exact O(n^2) count -> d_perm).
//  - 256 CTAs x 128 threads; CTA owns ranks {2p, 2p+1} (similar lengths):
//      warp0: fwd A | warp1: bwd A | warp2: fwd B | warp3: bwd B
//    -> one working warp per SMSP; ~254 regs -> 2 CTAs/SM, all resident.
//  - placement over bid%148 residue classes: bids 108..147 host ONE CTA ->
//    give them the 40 longest pairs (critical chain gets a private SMSP).
// Step core: source-forced 16x ld.shared.v2.b64 front-batch, 8 named f32x2
// accumulators, deferred 4-step exact power-of-2 rescale.
// logZ = (ktF+ktB)*ln2 + log( sum_j pF[j] * pB[j] ).

#define CRF_B 512
#define CRF_T 1024
#define CRF_L 64
#define C_LOG2E 1.4426950408889634f
#define C_LN2   0.6931471805599453f
#define FULLM  0xffffffffu

using u64 = unsigned long long;

__device__ int d_perm[CRF_B];            // rank -> batch index

__device__ __forceinline__ float ex2f(float x) {
    float r; asm("ex2.approx.f32 %0, %1;" : "=f"(r) : "f"(x)); return r;
}
__device__ __forceinline__ u64 packf2(float lo, float hi) {
    u64 r; asm("mov.b64 %0, {%1, %2};" : "=l"(r) : "f"(lo), "f"(hi)); return r;
}
__device__ __forceinline__ void unpackf2(u64 v, float& lo, float& hi) {
    asm("mov.b64 {%0, %1}, %2;" : "=f"(lo), "=f"(hi) : "l"(v));
}
__device__ __forceinline__ uint32_t smem_u32(const void* p) {
    uint32_t a;
    asm("{ .reg .u64 t; cvta.to.shared.u64 t, %1; cvt.u32.u64 %0, t; }"
        : "=r"(a) : "l"(p));
    return a;
}
#define FMA2(acc, a, b) \
    asm("fma.rn.f32x2 %0, %1, %2, %0;" : "+l"(acc) : "l"(a), "l"(b))
#define ADD2(acc, a) \
    asm("add.rn.f32x2 %0, %0, %1;" : "+l"(acc) : "l"(a))
#define LDSV2(lo, hi, addr) \
    asm volatile("ld.shared.v2.b64 {%0, %1}, [%2];" \
                 : "=l"(lo), "=l"(hi) : "r"(addr))

// ---- pre-kernel: exact descending-length ranking (O(n^2) count) ----
__global__ void __launch_bounds__(CRF_B)
rank_kernel(const int* __restrict__ lens)
{
    __shared__ int sl[CRF_B];
    const int i = threadIdx.x;
    sl[i] = lens[i];
    __syncthreads();
    const int li = sl[i];
    int cnt = 0;
#pragma unroll 8
    for (int j = 0; j < CRF_B; j++) {
        int lj = sl[j];
        cnt += (lj > li) || (lj == li && j < i);
    }
    d_perm[cnt] = i;                      // bijection: rank -> batch
}

// ---- R14 step minus __syncwarp ----
// FOLD: consume mu (recorded 3+ steps ago), fold exact 2^-k into el.
// REC: REDUX.MAX of new p into mu (no consumer this step).
template <bool FOLD, bool REC>
__device__ __forceinline__ void crf_step(
    float2 lg,
    const u64 (&Ea)[32], const u64 (&Eb)[32],
    uint32_t rda, uint32_t wra,
    int lane, int& ktot, unsigned& mu)
{
    float elA = ex2f(lg.x * C_LOG2E);
    float elB = ex2f(lg.y * C_LOG2E);
    if (FOLD) {
        int k = (int)(mu >> 23) - 127;
        ktot += k;
        float s = __int_as_float((127 - k) << 23);   // exact 2^-k
        elA *= s;
        elB *= s;
    }

    u64 p[32];
#pragma unroll
    for (int i = 0; i < 16; i++)
        LDSV2(p[2 * i], p[2 * i + 1], rda + 16u * i);

    u64 a0 = 0ull, a1 = 0ull, a2 = 0ull, a3 = 0ull;
    u64 b0 = 0ull, b1 = 0ull, b2 = 0ull, b3 = 0ull;
#pragma unroll
    for (int jj = 0; jj < 32; jj += 4) {
        FMA2(a0, Ea[jj],     p[jj]);
        FMA2(b0, Eb[jj],     p[jj]);
        FMA2(a1, Ea[jj + 1], p[jj + 1]);
        FMA2(b1, Eb[jj + 1], p[jj + 1]);
        FMA2(a2, Ea[jj + 2], p[jj + 2]);
        FMA2(b2, Eb[jj + 2], p[jj + 2]);
        FMA2(a3, Ea[jj + 3], p[jj + 3]);
        FMA2(b3, Eb[jj + 3], p[jj + 3]);
    }
    ADD2(a0, a1); ADD2(a2, a3); ADD2(a0, a2);
    ADD2(b0, b1); ADD2(b2, b3); ADD2(b0, b2);
    float ax, ay, bx, by;
    unpackf2(a0, ax, ay);
    unpackf2(b0, bx, by);
    float pA = (ax + ay) * elA;
    float pB = (bx + by) * elB;

    asm volatile("st.shared.b64 [%0], %1;"
                 :: "r"(wra + 8u * (uint32_t)lane), "l"(packf2(pA, pB)));

    if (REC) {
        mu = __reduce_max_sync(FULLM, __float_as_uint(fmaxf(pA, pB)));
    }
    // NO __syncwarp: single converged warp; volatile asm pins STS->LDS
    // program order and the per-warp LSU is in-order.
}

template <int SGN>
__device__ __forceinline__ int run_chain(
    const float2* __restrict__ lgp, int nlog, bool bare,
    const u64 (&Ea)[32], const u64 (&Eb)[32],
    uint32_t b0a, uint32_t b1a, int lane)
{
    int      ktot = 0;
    unsigned mu   = 0x3f800000u;           // 1.0f bits -> first fold k=0

    float2 q0, q1, q2, q3;
    if (nlog > 0) q0 = __ldg(lgp);
    if (nlog > 1) q1 = __ldg(lgp + SGN * 32);
    if (nlog > 2) q2 = __ldg(lgp + SGN * 64);
    if (nlog > 3) q3 = __ldg(lgp + SGN * 96);

    int t = 0;
    for (; t + 4 <= nlog; t += 4) {
        float2 g;
        g = q0; if (t + 4 < nlog) q0 = __ldg(lgp + (ptrdiff_t)SGN * (t + 4) * 32);
        crf_step<true,  false>(g, Ea, Eb, b0a, b1a, lane, ktot, mu);
        g = q1; if (t + 5 < nlog) q1 = __ldg(lgp + (ptrdiff_t)SGN * (t + 5) * 32);
        crf_step<false, false>(g, Ea, Eb, b1a, b0a, lane, ktot, mu);
        g = q2; if (t + 6 < nlog) q2 = __ldg(lgp + (ptrdiff_t)SGN * (t + 6) * 32);
        crf_step<false, false>(g, Ea, Eb, b0a, b1a, lane, ktot, mu);
        g = q3; if (t + 7 < nlog) q3 = __ldg(lgp + (ptrdiff_t)SGN * (t + 7) * 32);
        crf_step<false, true >(g, Ea, Eb, b1a, b0a, lane, ktot, mu);
    }

    bool pend = (t > 0);
    if (t < nlog) {
        if (pend) crf_step<true,  false>(q0, Ea, Eb, b0a, b1a, lane, ktot, mu);
        else      crf_step<false, false>(q0, Ea, Eb, b0a, b1a, lane, ktot, mu);
        pend = false; t++;
    }
    if (t < nlog) { crf_step<false, false>(q1, Ea, Eb, b1a, b0a, lane, ktot, mu); t++; }
    if (t < nlog) { crf_step<false, false>(q2, Ea, Eb, b0a, b1a, lane, ktot, mu); t++; }

    if (bare) {
        float2 g = make_float2(0.0f, 0.0f);
        bool odd = (t & 1);
        if (pend) {
            if (odd) crf_step<true, false>(g, Ea, Eb, b1a, b0a, lane, ktot, mu);
            else     crf_step<true, false>(g, Ea, Eb, b0a, b1a, lane, ktot, mu);
        } else {
            if (odd) crf_step<false, false>(g, Ea, Eb, b1a, b0a, lane, ktot, mu);
            else     crf_step<false, false>(g, Ea, Eb, b0a, b1a, lane, ktot, mu);
        }
    }
    return ktot;
}

__global__ void __launch_bounds__(128)
crf_fwd_kernel(const float* __restrict__ logits,
               const int*   __restrict__ lens,
               const float* __restrict__ trans,
               float*       __restrict__ out)
{
    __shared__ __align__(16) float2 sp[4][2][32];   // [warp][buffer][pair]
    __shared__ float2 fin[4][32];
    __shared__ int    ktW[4];

    const int w    = threadIdx.x >> 5;              // 0..3
    const int lane = threadIdx.x & 31;
    const int dir  = w & 1;                         // 0 = fwd, 1 = bwd

    // ---- placement: bid -> pair of ranks {2*pair, 2*pair+1} ----
    const int bid = blockIdx.x;                     // grid = 256
    int pair;
    if (bid >= 108 && bid < 148) pair = bid - 108;  // pairs 0..39 (longest)
    else if (bid < 108)          pair = bid + 40;   // pairs 40..147
    else                         pair = 255 - (bid - 148); // pairs 255..148
    const int b = d_perm[2 * pair + (w >> 1)];

    const uint32_t b0a = smem_u32(sp[w][0]);
    const uint32_t b1a = smem_u32(sp[w][1]);
    u64* wr0 = reinterpret_cast<u64*>(sp[w][0]);
    u64* wr1 = reinterpret_cast<u64*>(sp[w][1]);

    const int len = lens[b];
    const int m   = len >> 1;                       // fwd steps; bwd = len-m

    // ---- E in registers: fwd = rows of exp(trans); bwd = columns ----
    u64 Ea[32], Eb[32];
    if (dir == 0) {
        const float* ra = trans + (2 * lane)     * CRF_L;
        const float* rb = trans + (2 * lane + 1) * CRF_L;
#pragma unroll
        for (int jj = 0; jj < 32; jj++) {
            Ea[jj] = packf2(expf(ra[2 * jj]), expf(ra[2 * jj + 1]));
            Eb[jj] = packf2(expf(rb[2 * jj]), expf(rb[2 * jj + 1]));
        }
    } else {
        const float* ca = trans + (2 * lane);       // column 2*lane
        const float* cb = trans + (2 * lane + 1);   // column 2*lane+1
#pragma unroll
        for (int jj = 0; jj < 32; jj++) {
            Ea[jj] = packf2(expf(ca[(2 * jj) * CRF_L]), expf(ca[(2 * jj + 1) * CRF_L]));
            Eb[jj] = packf2(expf(cb[(2 * jj) * CRF_L]), expf(cb[(2 * jj + 1) * CRF_L]));
        }
    }

    const float2* base =
        reinterpret_cast<const float2*>(logits + (size_t)b * CRF_T * CRF_L) + lane;

    int kt;
    int nsteps;

    if (dir == 0) {
        // ---- forward: init = delta at start label 62, m logit steps ----
        wr0[lane] = packf2((2 * lane == 62) ? 1.0f : 0.0f,
                           (2 * lane + 1 == 62) ? 1.0f : 0.0f);
        __syncwarp();
        kt = run_chain<+1>(base, m, false, Ea, Eb, b0a, b1a, lane);
        nsteps = m;
    } else {
        // ---- backward: init v = el_{len-1} .* e63 (or e63 if len==0) ----
        float e63x = expf(trans[63 * CRF_L + 2 * lane]);
        float e63y = expf(trans[63 * CRF_L + 2 * lane + 1]);
        if (len >= 1) {
            float2 lgl = __ldg(base + (ptrdiff_t)(len - 1) * 32);
            e63x *= expf(lgl.x);
            e63y *= expf(lgl.y);
        }
        wr0[lane] = packf2(e63x, e63y);
        __syncwarp();
        const int nlog = (len >= 1) ? (len - m - 1) : 0;
        const float2* lgb = base + (ptrdiff_t)(len - 2) * 32;
        kt = run_chain<-1>(lgb, nlog, len >= 1, Ea, Eb, b0a, b1a, lane);
        nsteps = (len >= 1) ? (nlog + 1) : 0;
    }

    // ---- combine per batch: logZ = (ktF+ktB)*ln2 + log(sum pF[j]*pB[j]) ----
    float px, py;
    unpackf2((nsteps & 1) ? wr1[lane] : wr0[lane], px, py);
    fin[w][lane] = make_float2(px, py);
    if (lane == 0) ktW[w] = kt;
    __syncthreads();

    if (dir == 0) {
        float2 f = fin[w][lane];
        float2 g = fin[w + 1][lane];
        float dot = f.x * g.x + f.y * g.y;
#pragma unroll
        for (int o = 16; o > 0; o >>= 1)
            dot += __shfl_xor_sync(FULLM, dot, o);
        if (lane == 0)
            out[b] = (float)(ktW[w] + ktW[w + 1]) * C_LN2 + __logf(dot);
    }
}

extern "C" void kernel_launch(void* const* d_in, const int* in_sizes, int n_in,
                              void* d_out, int out_size)
{
    const float* logits = (const float*)d_in[0];   // [512,1024,64] f32
    const int*   lens   = (const int*)  d_in[1];   // [512] i32
    const float* trans  = (const float*)d_in[2];   // [64,64] f32
    float* out = (float*)d_out;                    // [512] f32

    rank_kernel<<<1, CRF_B>>>(lens);
    crf_fwd_kernel<<<CRF_B / 2, 128>>>(logits, lens, trans, out);
}